// round 4
// baseline (speedup 1.0000x reference)
#include <cuda_runtime.h>

#define NN 50000
#define NE 800000
#define D  128
#define EPSV 1e-5f

// ---------------- scratch (static device globals; no allocations) ----------------
__device__ float g_s[(size_t)NN * D];     // scatter accumulator
__device__ float g_h1[(size_t)NN * D];    // layer-1 activation
__device__ float g_hp[(size_t)NN * D];    // pre-norm GEMM output
__device__ float g_xres[(size_t)NN * D];  // x @ Wres^T
__device__ float g_cnt[NN];
__device__ float g_inv[NN];
__device__ float g_stats[2 * D];          // [0:128) col sums, [128:256) col sumsq
__device__ float g_np[3 * D];             // [0:128) a*mean, [128:256) w*rsqrt(var+eps), [256:384) b
__device__ float g_Bt1[2 * D * D];        // [Wl1;Wr1]^T  (k-major: Bt[k*D+j] = W[j,k])
__device__ float g_Bt2[2 * D * D];        // [Wl2;Wr2]^T
__device__ float g_Btr[D * D];            // Wres^T

// ---------------- weight transpose prep ----------------
__global__ void prep_weights(const float* __restrict__ Wl1, const float* __restrict__ Wr1,
                             const float* __restrict__ Wl2, const float* __restrict__ Wr2,
                             const float* __restrict__ Wres)
{
    int idx = blockIdx.x * blockDim.x + threadIdx.x;
    if (idx < 2 * D * D) {
        int k = idx / D, j = idx % D;
        g_Bt1[idx] = (k < D) ? Wl1[j * D + k] : Wr1[j * D + (k - D)];
        g_Bt2[idx] = (k < D) ? Wl2[j * D + k] : Wr2[j * D + (k - D)];
    } else {
        int t = idx - 2 * D * D;
        if (t < D * D) {
            int k = t / D, j = t % D;
            g_Btr[t] = Wres[j * D + k];
        }
    }
}

// ---------------- zeroing ----------------
__global__ void zero_kernel(int firstLayer)
{
    int idx = blockIdx.x * blockDim.x + threadIdx.x;
    if (idx < NN * D / 4)
        reinterpret_cast<float4*>(g_s)[idx] = make_float4(0.f, 0.f, 0.f, 0.f);
    if (idx < 2 * D) g_stats[idx] = 0.f;
    if (firstLayer && idx < NN) g_cnt[idx] = 0.f;
}

// ---------------- edge scatter: warp per edge, float4 vector atomics ----------------
// edge_index is int32 on device (JAX x64 disabled: jnp.int64 -> int32).
template <bool COUNT>
__global__ void scatter_kernel(const float* __restrict__ src_x,
                               const int* __restrict__ ei)
{
    int warp = (blockIdx.x * blockDim.x + threadIdx.x) >> 5;
    int lane = threadIdx.x & 31;
    if (warp >= NE) return;
    int s = __ldg(ei + warp);
    int d = __ldg(ei + NE + warp);
    if ((unsigned)s >= NN || (unsigned)d >= NN) return;  // robustness guard
    float4 v = __ldg(reinterpret_cast<const float4*>(src_x + (size_t)s * D) + lane);
    float* dp = g_s + (size_t)d * D + lane * 4;
    asm volatile("red.global.add.v4.f32 [%0], {%1,%2,%3,%4};"
                 :: "l"(dp), "f"(v.x), "f"(v.y), "f"(v.z), "f"(v.w) : "memory");
    if (COUNT && lane == 0) atomicAdd(&g_cnt[d], 1.0f);
}

__global__ void inv_kernel()
{
    int i = blockIdx.x * blockDim.x + threadIdx.x;
    if (i < NN) g_inv[i] = 1.0f / fmaxf(g_cnt[i], 1.0f);
}

// ---------------- fused SGEMM:  out[N,128] = [A0*inv | A1] @ Bt  (+bias) (+col stats) ----
// BM=128, BN=128, BK=8, 256 threads, 8x8 microtile.
__global__ __launch_bounds__(256, 2)
void gemm_kernel(const float* __restrict__ A0, int useInv,
                 const float* __restrict__ A1,
                 const float* __restrict__ Bt,
                 const float* __restrict__ bias,
                 float* __restrict__ out,
                 int K, int doStats)
{
    __shared__ float As[8][128];
    __shared__ float Bs[8][128];
    __shared__ float red[16][128];

    const int tid = threadIdx.x;
    const int tx = tid & 15, ty = tid >> 4;
    const int rowBase = blockIdx.x * 128;

    float c[8][8];
#pragma unroll
    for (int i = 0; i < 8; i++)
#pragma unroll
        for (int j = 0; j < 8; j++) c[i][j] = 0.f;

    const int lm = tid >> 1;           // row in tile 0..127
    const int lk = (tid & 1) * 4;      // k offset 0 or 4
    const int grow = rowBase + lm;
    float inv = 1.0f;
    if (useInv && grow < NN) inv = g_inv[grow];

    const int bk = tid >> 5;           // B tile: k row 0..7
    const int bn = (tid & 31) * 4;     // B tile: col

    for (int kb = 0; kb < K; kb += 8) {
        float4 av = make_float4(0.f, 0.f, 0.f, 0.f);
        if (grow < NN) {
            int kk = kb + lk;
            if (kk < D) {
                av = *reinterpret_cast<const float4*>(A0 + (size_t)grow * D + kk);
                if (useInv) { av.x *= inv; av.y *= inv; av.z *= inv; av.w *= inv; }
            } else {
                av = *reinterpret_cast<const float4*>(A1 + (size_t)grow * D + (kk - D));
            }
        }
        As[lk + 0][lm] = av.x; As[lk + 1][lm] = av.y;
        As[lk + 2][lm] = av.z; As[lk + 3][lm] = av.w;
        *reinterpret_cast<float4*>(&Bs[bk][bn]) =
            *reinterpret_cast<const float4*>(Bt + (size_t)(kb + bk) * D + bn);
        __syncthreads();

#pragma unroll
        for (int k = 0; k < 8; k++) {
            float a[8], b[8];
            *reinterpret_cast<float4*>(a)     = *reinterpret_cast<float4*>(&As[k][ty * 8]);
            *reinterpret_cast<float4*>(a + 4) = *reinterpret_cast<float4*>(&As[k][ty * 8 + 4]);
            *reinterpret_cast<float4*>(b)     = *reinterpret_cast<float4*>(&Bs[k][tx * 8]);
            *reinterpret_cast<float4*>(b + 4) = *reinterpret_cast<float4*>(&Bs[k][tx * 8 + 4]);
#pragma unroll
            for (int i = 0; i < 8; i++)
#pragma unroll
                for (int j = 0; j < 8; j++) c[i][j] += a[i] * b[j];
        }
        __syncthreads();
    }

    // bias
    if (bias) {
        float bv[8];
#pragma unroll
        for (int j = 0; j < 8; j++) bv[j] = __ldg(bias + tx * 8 + j);
#pragma unroll
        for (int i = 0; i < 8; i++)
#pragma unroll
            for (int j = 0; j < 8; j++) c[i][j] += bv[j];
    }

    // store
#pragma unroll
    for (int i = 0; i < 8; i++) {
        int row = rowBase + ty * 8 + i;
        if (row < NN) {
            *reinterpret_cast<float4*>(out + (size_t)row * D + tx * 8)     =
                make_float4(c[i][0], c[i][1], c[i][2], c[i][3]);
            *reinterpret_cast<float4*>(out + (size_t)row * D + tx * 8 + 4) =
                make_float4(c[i][4], c[i][5], c[i][6], c[i][7]);
        }
    }

    // fused per-column stats (sum, sumsq) for GraphNorm
    if (doStats) {
        float ps[8], pq[8];
#pragma unroll
        for (int j = 0; j < 8; j++) { ps[j] = 0.f; pq[j] = 0.f; }
#pragma unroll
        for (int i = 0; i < 8; i++) {
            int row = rowBase + ty * 8 + i;
            if (row < NN) {
#pragma unroll
                for (int j = 0; j < 8; j++) { float v = c[i][j]; ps[j] += v; pq[j] += v * v; }
            }
        }
#pragma unroll
        for (int j = 0; j < 8; j++) red[ty][tx * 8 + j] = ps[j];
        __syncthreads();
        if (tid < D) {
            float s = 0.f;
#pragma unroll
            for (int t = 0; t < 16; t++) s += red[t][tid];
            atomicAdd(&g_stats[tid], s);
        }
        __syncthreads();
#pragma unroll
        for (int j = 0; j < 8; j++) red[ty][tx * 8 + j] = pq[j];
        __syncthreads();
        if (tid < D) {
            float s = 0.f;
#pragma unroll
            for (int t = 0; t < 16; t++) s += red[t][tid];
            atomicAdd(&g_stats[D + tid], s);
        }
    }
}

// ---------------- GraphNorm param finalize ----------------
__global__ void finalize_kernel(const float* __restrict__ w,
                                const float* __restrict__ b,
                                const float* __restrict__ a)
{
    int j = threadIdx.x;
    const float invN = 1.0f / (float)NN;
    float mean = g_stats[j] * invN;
    float ex2  = g_stats[D + j] * invN;
    float aj = a[j];
    float var = ex2 - (2.0f * aj - aj * aj) * mean * mean;
    g_np[j]         = aj * mean;
    g_np[D + j]     = w[j] * rsqrtf(var + EPSV);
    g_np[2 * D + j] = b[j];
}

// ---------------- normalize + ReLU (+ final residual add) ----------------
template <bool FINAL>
__global__ void norm_kernel(const float* __restrict__ h, float* __restrict__ o,
                            const float* __restrict__ bres)
{
    int idx = blockIdx.x * blockDim.x + threadIdx.x;   // over NN * 32 float4s
    if (idx >= NN * (D / 4)) return;
    int col = (idx & 31) * 4;
    float4 v = reinterpret_cast<const float4*>(h)[idx];
    float4 r;
    r.x = fmaxf(g_np[D + col + 0] * (v.x - g_np[col + 0]) + g_np[2 * D + col + 0], 0.f);
    r.y = fmaxf(g_np[D + col + 1] * (v.y - g_np[col + 1]) + g_np[2 * D + col + 1], 0.f);
    r.z = fmaxf(g_np[D + col + 2] * (v.z - g_np[col + 2]) + g_np[2 * D + col + 2], 0.f);
    r.w = fmaxf(g_np[D + col + 3] * (v.w - g_np[col + 3]) + g_np[2 * D + col + 3], 0.f);
    if (FINAL) {
        float4 xr = reinterpret_cast<const float4*>(g_xres)[idx];
        r.x += xr.x + __ldg(bres + col + 0);
        r.y += xr.y + __ldg(bres + col + 1);
        r.z += xr.z + __ldg(bres + col + 2);
        r.w += xr.w + __ldg(bres + col + 3);
    }
    reinterpret_cast<float4*>(o)[idx] = r;
}

// ---------------- launch ----------------
extern "C" void kernel_launch(void* const* d_in, const int* in_sizes, int n_in,
                              void* d_out, int out_size)
{
    const float* x    = (const float*)d_in[0];
    const int*   ei   = (const int*)d_in[1];          // int32 (JAX x64 disabled)
    const float* Wl1  = (const float*)d_in[2];
    const float* bl1  = (const float*)d_in[3];
    const float* Wr1  = (const float*)d_in[4];
    const float* Wl2  = (const float*)d_in[5];
    const float* bl2  = (const float*)d_in[6];
    const float* Wr2  = (const float*)d_in[7];
    const float* g1w  = (const float*)d_in[8];
    const float* g1b  = (const float*)d_in[9];
    const float* g1a  = (const float*)d_in[10];
    const float* g2w  = (const float*)d_in[11];
    const float* g2b  = (const float*)d_in[12];
    const float* g2a  = (const float*)d_in[13];
    const float* Wres = (const float*)d_in[14];
    const float* bres = (const float*)d_in[15];
    float* out = (float*)d_out;

    float *p_s, *p_h1, *p_hp, *p_xres, *p_Bt1, *p_Bt2, *p_Btr;
    cudaGetSymbolAddress((void**)&p_s,    g_s);
    cudaGetSymbolAddress((void**)&p_h1,   g_h1);
    cudaGetSymbolAddress((void**)&p_hp,   g_hp);
    cudaGetSymbolAddress((void**)&p_xres, g_xres);
    cudaGetSymbolAddress((void**)&p_Bt1,  g_Bt1);
    cudaGetSymbolAddress((void**)&p_Bt2,  g_Bt2);
    cudaGetSymbolAddress((void**)&p_Btr,  g_Btr);

    const int zeroBlocks = (NN * D / 4 + 255) / 256;
    const int gemmBlocks = (NN + 127) / 128;
    const int normBlocks = (NN * (D / 4) + 255) / 256;

    prep_weights<<<(3 * D * D + 255) / 256, 256>>>(Wl1, Wr1, Wl2, Wr2, Wres);

    // ---- layer 1 ----
    zero_kernel<<<zeroBlocks, 256>>>(1);
    scatter_kernel<true><<<NE / 8, 256>>>(x, ei);
    inv_kernel<<<(NN + 255) / 256, 256>>>();
    gemm_kernel<<<gemmBlocks, 256>>>(p_s, 1, x, p_Bt1, bl1, p_hp, 2 * D, 1);
    gemm_kernel<<<gemmBlocks, 256>>>(x, 0, x, p_Btr, nullptr, p_xres, D, 0);
    finalize_kernel<<<1, D>>>(g1w, g1b, g1a);
    norm_kernel<false><<<normBlocks, 256>>>(p_hp, p_h1, nullptr);

    // ---- layer 2 ----
    zero_kernel<<<zeroBlocks, 256>>>(0);
    scatter_kernel<false><<<NE / 8, 256>>>(p_h1, ei);
    gemm_kernel<<<gemmBlocks, 256>>>(p_s, 1, p_h1, p_Bt2, bl2, p_hp, 2 * D, 1);
    finalize_kernel<<<1, D>>>(g2w, g2b, g2a);
    norm_kernel<true><<<normBlocks, 256>>>(p_hp, out, bres);
}

// round 6
// speedup vs baseline: 1.4122x; 1.4122x over previous
#include <cuda_runtime.h>
#include <cstdint>

#define NN 50000
#define NE 800000
#define D  128
#define EPSV 1e-5f

// ---------------- scratch ----------------
__device__ float g_s[(size_t)NN * D];
__device__ float g_h1[(size_t)NN * D];
__device__ float g_hp[(size_t)NN * D];
__device__ float g_xres[(size_t)NN * D];
__device__ float g_cnt[NN];
__device__ float g_inv[NN];
__device__ float g_stats[2 * D];
__device__ float g_np[3 * D];

// ---------------- zero ----------------
__global__ void zero_kernel(int firstLayer)
{
    int idx = blockIdx.x * blockDim.x + threadIdx.x;
    if (idx < NN * D / 4)
        reinterpret_cast<float4*>(g_s)[idx] = make_float4(0.f, 0.f, 0.f, 0.f);
    if (idx < 2 * D) g_stats[idx] = 0.f;
    if (firstLayer && idx < NN) g_cnt[idx] = 0.f;
}

// ---------------- edge scatter (int32 indices) ----------------
template <bool COUNT>
__global__ void scatter_kernel(const float* __restrict__ src_x,
                               const int* __restrict__ ei)
{
    int warp = (blockIdx.x * blockDim.x + threadIdx.x) >> 5;
    int lane = threadIdx.x & 31;
    if (warp >= NE) return;
    int s = __ldg(ei + warp);
    int d = __ldg(ei + NE + warp);
    if ((unsigned)s >= NN || (unsigned)d >= NN) return;
    float4 v = __ldg(reinterpret_cast<const float4*>(src_x + (size_t)s * D) + lane);
    float* dp = g_s + (size_t)d * D + lane * 4;
    asm volatile("red.global.add.v4.f32 [%0], {%1,%2,%3,%4};"
                 :: "l"(dp), "f"(v.x), "f"(v.y), "f"(v.z), "f"(v.w) : "memory");
    if (COUNT && lane == 0) atomicAdd(&g_cnt[d], 1.0f);
}

__global__ void inv_kernel()
{
    int i = blockIdx.x * blockDim.x + threadIdx.x;
    if (i < NN) g_inv[i] = 1.0f / fmaxf(g_cnt[i], 1.0f);
}

// ---------------- tf32 helpers ----------------
__device__ __forceinline__ uint32_t f2tf32(float f) {
    uint32_t r;
    asm("cvt.rna.tf32.f32 %0, %1;" : "=r"(r) : "f"(f));
    return r;
}

__device__ __forceinline__ void mma_tf32(float* d, const uint32_t* a,
                                         uint32_t b0, uint32_t b1) {
    asm volatile(
        "mma.sync.aligned.m16n8k8.row.col.f32.tf32.tf32.f32 "
        "{%0,%1,%2,%3}, {%4,%5,%6,%7}, {%8,%9}, {%0,%1,%2,%3};"
        : "+f"(d[0]), "+f"(d[1]), "+f"(d[2]), "+f"(d[3])
        : "r"(a[0]), "r"(a[1]), "r"(a[2]), "r"(a[3]), "r"(b0), "r"(b1));
}

// ---------------- mma.sync tf32 GEMM ----------------
// out[NN,128] = [A0(*inv) | A1] @ [W0;W1]^T (+bias)
// BM=128, BN=128, chunks of 32 K-cols, double-buffered SMEM.
// SMEM: As[2][128][36], Bs[2][128][36] (floats) = 73728 bytes dynamic.
#define KP 36
#define BUFF (128 * KP)

template <int KC, bool CONCAT, bool USEINV>
__global__ __launch_bounds__(256, 1)
void gemm_mma(const float* __restrict__ A0, const float* __restrict__ A1,
              const float* __restrict__ W0, const float* __restrict__ W1,
              const float* __restrict__ bias, float* __restrict__ out)
{
    extern __shared__ float sm[];
    float* As = sm;                    // [2][128][KP]
    float* Bs = sm + 2 * BUFF;         // [2][128][KP]

    const int tid = threadIdx.x;
    const int wid = tid >> 5, lane = tid & 31;
    const int warpM = wid >> 1;        // 0..3 -> 32-row slab
    const int warpN = wid & 1;         // 0..1 -> 64-col slab
    const int gid = lane >> 2;         // 0..7
    const int tg  = lane & 3;          // 0..3
    const int rowBase = blockIdx.x * 128;

    float acc[2][8][4];
#pragma unroll
    for (int m = 0; m < 2; m++)
#pragma unroll
        for (int n = 0; n < 8; n++)
#pragma unroll
            for (int q = 0; q < 4; q++) acc[m][n][q] = 0.f;

    // per-thread staging: 4 float4 of A, 4 float4 of B per chunk
    float4 ra[4], rb[4];

    auto loadChunk = [&](int kc) {
#pragma unroll
        for (int i = 0; i < 4; i++) {
            int f = tid + i * 256;         // 0..1023
            int r = f >> 3;                // 0..127
            int k = kc * 32 + (f & 7) * 4; // k col
            // A
            int rg = rowBase + r;
            float4 va = make_float4(0.f, 0.f, 0.f, 0.f);
            if (rg < NN) {
                if (CONCAT && k >= D) {
                    va = __ldg(reinterpret_cast<const float4*>(A1 + (size_t)rg * D + (k - D)));
                } else {
                    va = __ldg(reinterpret_cast<const float4*>(A0 + (size_t)rg * D + k));
                    if (USEINV) {
                        float s = g_inv[rg];
                        va.x *= s; va.y *= s; va.z *= s; va.w *= s;
                    }
                }
            }
            ra[i] = va;
            // B (weights, rows are output cols n=r)
            const float* wsrc = (CONCAT && k >= D) ? (W1 + r * D + (k - D))
                                                   : (W0 + r * D + k);
            rb[i] = __ldg(reinterpret_cast<const float4*>(wsrc));
        }
    };

    auto stsChunk = [&](int buf) {
#pragma unroll
        for (int i = 0; i < 4; i++) {
            int f = tid + i * 256;
            int r = f >> 3;
            int kg = (f & 7) * 4;
            uint4 ua = make_uint4(f2tf32(ra[i].x), f2tf32(ra[i].y),
                                  f2tf32(ra[i].z), f2tf32(ra[i].w));
            uint4 ub = make_uint4(f2tf32(rb[i].x), f2tf32(rb[i].y),
                                  f2tf32(rb[i].z), f2tf32(rb[i].w));
            *reinterpret_cast<uint4*>(&As[buf * BUFF + r * KP + kg]) = ua;
            *reinterpret_cast<uint4*>(&Bs[buf * BUFF + r * KP + kg]) = ub;
        }
    };

    loadChunk(0);
    stsChunk(0);
    __syncthreads();

    for (int kc = 0; kc < KC; kc++) {
        if (kc + 1 < KC) loadChunk(kc + 1);
        const int buf = kc & 1;
        const float* ab = &As[buf * BUFF];
        const float* bb = &Bs[buf * BUFF];
#pragma unroll
        for (int ks = 0; ks < 4; ks++) {
            const int kb = ks * 8;
            uint32_t a[2][4];
#pragma unroll
            for (int m = 0; m < 2; m++) {
                int r = warpM * 32 + m * 16 + gid;
                a[m][0] = __float_as_uint(ab[r * KP + kb + tg]);
                a[m][1] = __float_as_uint(ab[(r + 8) * KP + kb + tg]);
                a[m][2] = __float_as_uint(ab[r * KP + kb + tg + 4]);
                a[m][3] = __float_as_uint(ab[(r + 8) * KP + kb + tg + 4]);
            }
#pragma unroll
            for (int n = 0; n < 8; n++) {
                int c = warpN * 64 + n * 8 + gid;
                uint32_t b0 = __float_as_uint(bb[c * KP + kb + tg]);
                uint32_t b1 = __float_as_uint(bb[c * KP + kb + tg + 4]);
                mma_tf32(acc[0][n], a[0], b0, b1);
                mma_tf32(acc[1][n], a[1], b0, b1);
            }
        }
        if (kc + 1 < KC) {
            stsChunk((kc + 1) & 1);
            __syncthreads();
        }
    }

    // ---- epilogue ----
    const bool hasBias = (bias != nullptr);
#pragma unroll
    for (int m = 0; m < 2; m++) {
#pragma unroll
        for (int half = 0; half < 2; half++) {
            int row = rowBase + warpM * 32 + m * 16 + gid + half * 8;
            if (row < NN) {
#pragma unroll
                for (int n = 0; n < 8; n++) {
                    int col = warpN * 64 + n * 8 + tg * 2;
                    float2 v;
                    v.x = acc[m][n][half * 2 + 0];
                    v.y = acc[m][n][half * 2 + 1];
                    if (hasBias) {
                        v.x += __ldg(bias + col + 0);
                        v.y += __ldg(bias + col + 1);
                    }
                    *reinterpret_cast<float2*>(out + (size_t)row * D + col) = v;
                }
            }
        }
    }
}

// ---------------- column stats (sum, sumsq) ----------------
__global__ void stats_kernel(const float* __restrict__ h)
{
    int j = threadIdx.x;
    float s = 0.f, q = 0.f;
    for (int row = blockIdx.x; row < NN; row += gridDim.x) {
        float v = h[(size_t)row * D + j];
        s += v; q += v * v;
    }
    atomicAdd(&g_stats[j], s);
    atomicAdd(&g_stats[D + j], q);
}

// ---------------- GraphNorm finalize ----------------
__global__ void finalize_kernel(const float* __restrict__ w,
                                const float* __restrict__ b,
                                const float* __restrict__ a)
{
    int j = threadIdx.x;
    const float invN = 1.0f / (float)NN;
    float mean = g_stats[j] * invN;
    float ex2  = g_stats[D + j] * invN;
    float aj = a[j];
    float var = ex2 - (2.0f * aj - aj * aj) * mean * mean;
    g_np[j]         = aj * mean;
    g_np[D + j]     = w[j] * rsqrtf(var + EPSV);
    g_np[2 * D + j] = b[j];
}

// ---------------- normalize + ReLU (+ final residual) ----------------
template <bool FINAL>
__global__ void norm_kernel(const float* __restrict__ h, float* __restrict__ o,
                            const float* __restrict__ bres)
{
    int idx = blockIdx.x * blockDim.x + threadIdx.x;
    if (idx >= NN * (D / 4)) return;
    int col = (idx & 31) * 4;
    float4 v = reinterpret_cast<const float4*>(h)[idx];
    float4 r;
    r.x = fmaxf(g_np[D + col + 0] * (v.x - g_np[col + 0]) + g_np[2 * D + col + 0], 0.f);
    r.y = fmaxf(g_np[D + col + 1] * (v.y - g_np[col + 1]) + g_np[2 * D + col + 1], 0.f);
    r.z = fmaxf(g_np[D + col + 2] * (v.z - g_np[col + 2]) + g_np[2 * D + col + 2], 0.f);
    r.w = fmaxf(g_np[D + col + 3] * (v.w - g_np[col + 3]) + g_np[2 * D + col + 3], 0.f);
    if (FINAL) {
        float4 xr = reinterpret_cast<const float4*>(g_xres)[idx];
        r.x += xr.x + __ldg(bres + col + 0);
        r.y += xr.y + __ldg(bres + col + 1);
        r.z += xr.z + __ldg(bres + col + 2);
        r.w += xr.w + __ldg(bres + col + 3);
    }
    reinterpret_cast<float4*>(o)[idx] = r;
}

// ---------------- launch ----------------
extern "C" void kernel_launch(void* const* d_in, const int* in_sizes, int n_in,
                              void* d_out, int out_size)
{
    const float* x    = (const float*)d_in[0];
    const int*   ei   = (const int*)d_in[1];
    const float* Wl1  = (const float*)d_in[2];
    const float* bl1  = (const float*)d_in[3];
    const float* Wr1  = (const float*)d_in[4];
    const float* Wl2  = (const float*)d_in[5];
    const float* bl2  = (const float*)d_in[6];
    const float* Wr2  = (const float*)d_in[7];
    const float* g1w  = (const float*)d_in[8];
    const float* g1b  = (const float*)d_in[9];
    const float* g1a  = (const float*)d_in[10];
    const float* g2w  = (const float*)d_in[11];
    const float* g2b  = (const float*)d_in[12];
    const float* g2a  = (const float*)d_in[13];
    const float* Wres = (const float*)d_in[14];
    const float* bres = (const float*)d_in[15];
    float* out = (float*)d_out;

    float *p_s, *p_h1, *p_hp, *p_xres;
    cudaGetSymbolAddress((void**)&p_s,    g_s);
    cudaGetSymbolAddress((void**)&p_h1,   g_h1);
    cudaGetSymbolAddress((void**)&p_hp,   g_hp);
    cudaGetSymbolAddress((void**)&p_xres, g_xres);

    const int SMEM = 4 * BUFF * (int)sizeof(float);  // 73728
    cudaFuncSetAttribute(gemm_mma<8, true, true>,
                         cudaFuncAttributeMaxDynamicSharedMemorySize, SMEM);
    cudaFuncSetAttribute(gemm_mma<4, false, false>,
                         cudaFuncAttributeMaxDynamicSharedMemorySize, SMEM);

    const int zeroBlocks = (NN * D / 4 + 255) / 256;
    const int gemmBlocks = (NN + 127) / 128;   // 391
    const int normBlocks = (NN * (D / 4) + 255) / 256;

    // ---- layer 1 ----
    zero_kernel<<<zeroBlocks, 256>>>(1);
    scatter_kernel<true><<<NE / 8, 256>>>(x, ei);
    inv_kernel<<<(NN + 255) / 256, 256>>>();
    gemm_mma<8, true, true><<<gemmBlocks, 256, SMEM>>>(p_s, x, Wl1, Wr1, bl1, p_hp);
    gemm_mma<4, false, false><<<gemmBlocks, 256, SMEM>>>(x, x, Wres, Wres, nullptr, p_xres);
    stats_kernel<<<1024, 128>>>(p_hp);
    finalize_kernel<<<1, D>>>(g1w, g1b, g1a);
    norm_kernel<false><<<normBlocks, 256>>>(p_hp, p_h1, nullptr);

    // ---- layer 2 ----
    zero_kernel<<<zeroBlocks, 256>>>(0);
    scatter_kernel<false><<<NE / 8, 256>>>(p_h1, ei);
    gemm_mma<8, true, true><<<gemmBlocks, 256, SMEM>>>(p_s, p_h1, Wl2, Wr2, bl2, p_hp);
    stats_kernel<<<1024, 128>>>(p_hp);
    finalize_kernel<<<1, D>>>(g2w, g2b, g2a);
    norm_kernel<true><<<normBlocks, 256>>>(p_hp, out, bres);
}

// round 7
// speedup vs baseline: 1.6747x; 1.1859x over previous
#include <cuda_runtime.h>
#include <cstdint>

#define NN 50000
#define NE 800000
#define D  128
#define EPSV 1e-5f

// ---------------- scratch ----------------
__device__ float g_s[(size_t)NN * D];
__device__ float g_hp[(size_t)NN * D];
__device__ float g_xres[(size_t)NN * D];
__device__ float g_cnt[NN];
__device__ float g_inv[NN];
__device__ float g_stats[2 * D];
__device__ float g_np[3 * D];   // [0:128) a*mean, [128:256) w*rsqrt, [256:384) b

// ---------------- zero (once) ----------------
__global__ void zero_kernel()
{
    int idx = blockIdx.x * blockDim.x + threadIdx.x;
    if (idx < NN * D / 4)
        reinterpret_cast<float4*>(g_s)[idx] = make_float4(0.f, 0.f, 0.f, 0.f);
    if (idx < 2 * D) g_stats[idx] = 0.f;
    if (idx < NN) g_cnt[idx] = 0.f;
}

// ---------------- edge scatter; NORM applies graphnorm+relu to gathered row ----
template <bool COUNT, bool NORM>
__global__ void scatter_kernel(const float* __restrict__ src_x,
                               const int* __restrict__ ei)
{
    int warp = (blockIdx.x * blockDim.x + threadIdx.x) >> 5;
    int lane = threadIdx.x & 31;
    if (warp >= NE) return;
    int s = __ldg(ei + warp);
    int d = __ldg(ei + NE + warp);
    if ((unsigned)s >= NN || (unsigned)d >= NN) return;
    float4 v = __ldg(reinterpret_cast<const float4*>(src_x + (size_t)s * D) + lane);
    if (NORM) {
        float4 nm = __ldg(reinterpret_cast<const float4*>(g_np) + lane);
        float4 nw = __ldg(reinterpret_cast<const float4*>(g_np + D) + lane);
        float4 nb = __ldg(reinterpret_cast<const float4*>(g_np + 2 * D) + lane);
        v.x = fmaxf(nw.x * (v.x - nm.x) + nb.x, 0.f);
        v.y = fmaxf(nw.y * (v.y - nm.y) + nb.y, 0.f);
        v.z = fmaxf(nw.z * (v.z - nm.z) + nb.z, 0.f);
        v.w = fmaxf(nw.w * (v.w - nm.w) + nb.w, 0.f);
    }
    float* dp = g_s + (size_t)d * D + lane * 4;
    asm volatile("red.global.add.v4.f32 [%0], {%1,%2,%3,%4};"
                 :: "l"(dp), "f"(v.x), "f"(v.y), "f"(v.z), "f"(v.w) : "memory");
    if (COUNT && lane == 0) atomicAdd(&g_cnt[d], 1.0f);
}

__global__ void inv_kernel()
{
    int i = blockIdx.x * blockDim.x + threadIdx.x;
    if (i < NN) g_inv[i] = 1.0f / fmaxf(g_cnt[i], 1.0f);
}

// ---------------- tf32 helpers ----------------
__device__ __forceinline__ uint32_t f2tf32(float f) {
    uint32_t r;
    asm("cvt.rna.tf32.f32 %0, %1;" : "=r"(r) : "f"(f));
    return r;
}
__device__ __forceinline__ void mma_tf32(float* d, const uint32_t* a,
                                         uint32_t b0, uint32_t b1) {
    asm volatile(
        "mma.sync.aligned.m16n8k8.row.col.f32.tf32.tf32.f32 "
        "{%0,%1,%2,%3}, {%4,%5,%6,%7}, {%8,%9}, {%0,%1,%2,%3};"
        : "+f"(d[0]), "+f"(d[1]), "+f"(d[2]), "+f"(d[3])
        : "r"(a[0]), "r"(a[1]), "r"(a[2]), "r"(a[3]), "r"(b0), "r"(b1));
}
__device__ __forceinline__ uint32_t smem_u32(const void* p) {
    uint32_t a;
    asm("{ .reg .u64 t; cvta.to.shared.u64 t, %1; cvt.u32.u64 %0, t; }" : "=r"(a) : "l"(p));
    return a;
}
__device__ __forceinline__ void cp16(uint32_t dst, const void* src) {
    asm volatile("cp.async.cg.shared.global [%0], [%1], 16;" :: "r"(dst), "l"(src));
}
__device__ __forceinline__ void cp16z(uint32_t dst, const void* src, int sz) {
    asm volatile("cp.async.cg.shared.global [%0], [%1], 16, %2;"
                 :: "r"(dst), "l"(src), "r"(sz));
}

// ---------------- mma.sync tf32 GEMM (cp.async, fused epilogue) ----------------
// out[NN,128] = [A0(*inv) | normA1?(A1)] @ [W0;W1]^T (+bias)
// SMEM: As[2][128][36] fp32 raw, Bs[2][128][36], np[384].  75264 B dynamic.
#define KP 36
#define BUFF (128 * KP)

template <int KC, bool CONCAT, bool USEINV, bool STATS, bool ZEROA0, bool NORMA1>
__global__ __launch_bounds__(256, 2)
void gemm_mma(const float* __restrict__ A0, const float* __restrict__ A1,
              const float* __restrict__ W0, const float* __restrict__ W1,
              const float* __restrict__ bias, float* __restrict__ out)
{
    extern __shared__ float sm[];
    float* As  = sm;                 // [2][128][KP]
    float* Bs  = sm + 2 * BUFF;      // [2][128][KP]
    float* npS = sm + 4 * BUFF;      // [384]
    // stats scratch overlaps As (used only after all compute):
    float* sumS = sm;                // [4][128]
    float* sqS  = sm + 512;          // [4][128]

    const uint32_t sA = smem_u32(As);
    const uint32_t sB = smem_u32(Bs);
    const int tid = threadIdx.x;
    const int wid = tid >> 5, lane = tid & 31;
    const int warpM = wid >> 1;      // 0..3
    const int warpN = wid & 1;       // 0..1
    const int gid = lane >> 2;       // 0..7
    const int tg  = lane & 3;        // 0..3
    const int rowBase = blockIdx.x * 128;

    if (NORMA1) {
        for (int i = tid; i < 3 * D; i += 256) npS[i] = g_np[i];
    }

    float invr[2][2];
    if (USEINV) {
#pragma unroll
        for (int m = 0; m < 2; m++)
#pragma unroll
            for (int h = 0; h < 2; h++) {
                int row = rowBase + warpM * 32 + m * 16 + h * 8 + gid;
                invr[m][h] = (row < NN) ? g_inv[row] : 1.0f;
            }
    }

    float acc[2][8][4];
#pragma unroll
    for (int m = 0; m < 2; m++)
#pragma unroll
        for (int n = 0; n < 8; n++)
#pragma unroll
            for (int q = 0; q < 4; q++) acc[m][n][q] = 0.f;

    auto issueChunk = [&](int kc, int buf) {
#pragma unroll
        for (int i = 0; i < 4; i++) {
            int f = tid + i * 256;       // 0..1023
            int r = f >> 3;              // 0..127
            int kg = f & 7;
            int k = kc * 32 + kg * 4;
            uint32_t soff = (uint32_t)(buf * BUFF + r * KP + kg * 4) * 4u;
            // A
            int rg = rowBase + r;
            const float* gp;
            if (CONCAT && k >= D) gp = A1 + (size_t)rg * D + (k - D);
            else                  gp = A0 + (size_t)rg * D + k;
            int sz = 16;
            if (rg >= NN) { gp = A0; sz = 0; }
            cp16z(sA + soff, gp, sz);
            // B (weight row r = output col)
            const float* wp = (CONCAT && k >= D) ? (W1 + r * D + (k - D))
                                                 : (W0 + r * D + k);
            cp16(sB + soff, wp);
        }
        asm volatile("cp.async.commit_group;" ::: "memory");
    };

    issueChunk(0, 0);

#pragma unroll
    for (int kc = 0; kc < KC; kc++) {
        if (kc + 1 < KC) {
            issueChunk(kc + 1, (kc + 1) & 1);
            asm volatile("cp.async.wait_group 1;" ::: "memory");
        } else {
            asm volatile("cp.async.wait_group 0;" ::: "memory");
        }
        __syncthreads();

        const int buf = kc & 1;
        const float* ab = &As[buf * BUFF];
        const float* bb = &Bs[buf * BUFF];
        const bool isA1 = CONCAT && (kc >= 4);

#pragma unroll
        for (int ks = 0; ks < 4; ks++) {
            const int kb = ks * 8;
            // np params for this ks (NORMA1 path), k-cols kb+tg and kb+tg+4
            float nm0 = 0.f, nw0 = 1.f, nb0 = 0.f, nm1 = 0.f, nw1 = 1.f, nb1 = 0.f;
            if (NORMA1 && isA1) {
                int c0 = (kc - 4) * 32 + kb + tg;
                int c1 = c0 + 4;
                nm0 = npS[c0]; nw0 = npS[D + c0]; nb0 = npS[2 * D + c0];
                nm1 = npS[c1]; nw1 = npS[D + c1]; nb1 = npS[2 * D + c1];
            }
            uint32_t a[2][4];
#pragma unroll
            for (int m = 0; m < 2; m++) {
                int r1 = warpM * 32 + m * 16 + gid;
                int r2 = r1 + 8;
                float v0 = ab[r1 * KP + kb + tg];
                float v1 = ab[r2 * KP + kb + tg];
                float v2 = ab[r1 * KP + kb + tg + 4];
                float v3 = ab[r2 * KP + kb + tg + 4];
                if (USEINV && !isA1) {
                    v0 *= invr[m][0]; v1 *= invr[m][1];
                    v2 *= invr[m][0]; v3 *= invr[m][1];
                }
                if (NORMA1 && isA1) {
                    v0 = fmaxf(nw0 * (v0 - nm0) + nb0, 0.f);
                    v1 = fmaxf(nw0 * (v1 - nm0) + nb0, 0.f);
                    v2 = fmaxf(nw1 * (v2 - nm1) + nb1, 0.f);
                    v3 = fmaxf(nw1 * (v3 - nm1) + nb1, 0.f);
                }
                a[m][0] = f2tf32(v0); a[m][1] = f2tf32(v1);
                a[m][2] = f2tf32(v2); a[m][3] = f2tf32(v3);
            }
#pragma unroll
            for (int n = 0; n < 8; n++) {
                int c = warpN * 64 + n * 8 + gid;
                uint32_t b0 = f2tf32(bb[c * KP + kb + tg]);
                uint32_t b1 = f2tf32(bb[c * KP + kb + tg + 4]);
                mma_tf32(acc[0][n], a[0], b0, b1);
                mma_tf32(acc[1][n], a[1], b0, b1);
            }
        }
        __syncthreads();
    }

    // ---- epilogue: bias + store + (stats) ----
    const bool hasBias = (bias != nullptr);
    bool valid[2][2];
#pragma unroll
    for (int m = 0; m < 2; m++)
#pragma unroll
        for (int h = 0; h < 2; h++)
            valid[m][h] = (rowBase + warpM * 32 + m * 16 + h * 8 + gid) < NN;

#pragma unroll
    for (int n = 0; n < 8; n++) {
        int col = warpN * 64 + n * 8 + tg * 2;
        float b0 = hasBias ? __ldg(bias + col) : 0.f;
        float b1 = hasBias ? __ldg(bias + col + 1) : 0.f;
        float s0 = 0.f, s1 = 0.f, q0 = 0.f, q1 = 0.f;
#pragma unroll
        for (int m = 0; m < 2; m++) {
#pragma unroll
            for (int h = 0; h < 2; h++) {
                if (valid[m][h]) {
                    float v0 = acc[m][n][h * 2 + 0] + b0;
                    float v1 = acc[m][n][h * 2 + 1] + b1;
                    int row = rowBase + warpM * 32 + m * 16 + h * 8 + gid;
                    float2 st; st.x = v0; st.y = v1;
                    *reinterpret_cast<float2*>(out + (size_t)row * D + col) = st;
                    if (STATS) { s0 += v0; q0 += v0 * v0; s1 += v1; q1 += v1 * v1; }
                }
            }
        }
        if (STATS) {
#pragma unroll
            for (int sh = 4; sh <= 16; sh <<= 1) {
                s0 += __shfl_xor_sync(0xFFFFFFFFu, s0, sh);
                s1 += __shfl_xor_sync(0xFFFFFFFFu, s1, sh);
                q0 += __shfl_xor_sync(0xFFFFFFFFu, q0, sh);
                q1 += __shfl_xor_sync(0xFFFFFFFFu, q1, sh);
            }
            if (gid == 0) {
                sumS[warpM * 128 + col]     = s0;
                sumS[warpM * 128 + col + 1] = s1;
                sqS[warpM * 128 + col]      = q0;
                sqS[warpM * 128 + col + 1]  = q1;
            }
        }
    }

    if (STATS) {
        __syncthreads();
        if (tid < D) {
            float s = sumS[tid] + sumS[128 + tid] + sumS[256 + tid] + sumS[384 + tid];
            float q = sqS[tid] + sqS[128 + tid] + sqS[256 + tid] + sqS[384 + tid];
            atomicAdd(&g_stats[tid], s);
            atomicAdd(&g_stats[D + tid], q);
        }
    }

    if (ZEROA0) {
        // all A0 (= g_s) reads are done; zero this CTA's rows for layer 2
#pragma unroll 4
        for (int i = tid; i < 128 * 32; i += 256) {
            int row = rowBase + (i >> 5);
            if (row < NN)
                reinterpret_cast<float4*>(g_s + (size_t)row * D)[i & 31] =
                    make_float4(0.f, 0.f, 0.f, 0.f);
        }
    }
}

// ---------------- GraphNorm finalize (+ reset stats for next layer) ------------
__global__ void finalize_kernel(const float* __restrict__ w,
                                const float* __restrict__ b,
                                const float* __restrict__ a)
{
    int j = threadIdx.x;
    const float invN = 1.0f / (float)NN;
    float mean = g_stats[j] * invN;
    float ex2  = g_stats[D + j] * invN;
    float aj = a[j];
    float var = ex2 - (2.0f * aj - aj * aj) * mean * mean;
    g_np[j]         = aj * mean;
    g_np[D + j]     = w[j] * rsqrtf(var + EPSV);
    g_np[2 * D + j] = b[j];
    g_stats[j] = 0.f;
    g_stats[D + j] = 0.f;
}

// ---------------- final: norm2 + relu + residual + bres -> out ----------------
__global__ void final_kernel(const float* __restrict__ h, float* __restrict__ o,
                             const float* __restrict__ bres)
{
    int idx = blockIdx.x * blockDim.x + threadIdx.x;
    if (idx >= NN * (D / 4)) return;
    int col = (idx & 31) * 4;
    float4 v = reinterpret_cast<const float4*>(h)[idx];
    float4 xr = reinterpret_cast<const float4*>(g_xres)[idx];
    float4 r;
    r.x = fmaxf(g_np[D + col + 0] * (v.x - g_np[col + 0]) + g_np[2 * D + col + 0], 0.f)
          + xr.x + __ldg(bres + col + 0);
    r.y = fmaxf(g_np[D + col + 1] * (v.y - g_np[col + 1]) + g_np[2 * D + col + 1], 0.f)
          + xr.y + __ldg(bres + col + 1);
    r.z = fmaxf(g_np[D + col + 2] * (v.z - g_np[col + 2]) + g_np[2 * D + col + 2], 0.f)
          + xr.z + __ldg(bres + col + 2);
    r.w = fmaxf(g_np[D + col + 3] * (v.w - g_np[col + 3]) + g_np[2 * D + col + 3], 0.f)
          + xr.w + __ldg(bres + col + 3);
    reinterpret_cast<float4*>(o)[idx] = r;
}

// ---------------- launch ----------------
extern "C" void kernel_launch(void* const* d_in, const int* in_sizes, int n_in,
                              void* d_out, int out_size)
{
    const float* x    = (const float*)d_in[0];
    const int*   ei   = (const int*)d_in[1];
    const float* Wl1  = (const float*)d_in[2];
    const float* bl1  = (const float*)d_in[3];
    const float* Wr1  = (const float*)d_in[4];
    const float* Wl2  = (const float*)d_in[5];
    const float* bl2  = (const float*)d_in[6];
    const float* Wr2  = (const float*)d_in[7];
    const float* g1w  = (const float*)d_in[8];
    const float* g1b  = (const float*)d_in[9];
    const float* g1a  = (const float*)d_in[10];
    const float* g2w  = (const float*)d_in[11];
    const float* g2b  = (const float*)d_in[12];
    const float* g2a  = (const float*)d_in[13];
    const float* Wres = (const float*)d_in[14];
    const float* bres = (const float*)d_in[15];
    float* out = (float*)d_out;

    float *p_s, *p_hp;
    cudaGetSymbolAddress((void**)&p_s,  g_s);
    cudaGetSymbolAddress((void**)&p_hp, g_hp);
    float* p_xres;
    cudaGetSymbolAddress((void**)&p_xres, g_xres);

    const int SMEM = (4 * BUFF + 3 * D) * (int)sizeof(float);  // 75264
    cudaFuncSetAttribute((const void*)gemm_mma<8, true, true, true, true, false>,
                         cudaFuncAttributeMaxDynamicSharedMemorySize, SMEM);
    cudaFuncSetAttribute((const void*)gemm_mma<8, true, true, true, false, true>,
                         cudaFuncAttributeMaxDynamicSharedMemorySize, SMEM);
    cudaFuncSetAttribute((const void*)gemm_mma<4, false, false, false, false, false>,
                         cudaFuncAttributeMaxDynamicSharedMemorySize, SMEM);

    const int zeroBlocks = (NN * D / 4 + 255) / 256;
    const int gemmBlocks = (NN + 127) / 128;   // 391
    const int finBlocks  = (NN * (D / 4) + 255) / 256;

    // ---- layer 1 ----
    zero_kernel<<<zeroBlocks, 256>>>();
    scatter_kernel<true, false><<<NE / 8, 256>>>(x, ei);
    inv_kernel<<<(NN + 255) / 256, 256>>>();
    gemm_mma<8, true, true, true, true, false><<<gemmBlocks, 256, SMEM>>>(
        p_s, x, Wl1, Wr1, bl1, p_hp);                     // hp1 + stats + zero g_s
    gemm_mma<4, false, false, false, false, false><<<gemmBlocks, 256, SMEM>>>(
        x, x, Wres, Wres, nullptr, p_xres);               // xres
    finalize_kernel<<<1, D>>>(g1w, g1b, g1a);

    // ---- layer 2 (h1 never materialized: norm applied on the fly) ----
    scatter_kernel<false, true><<<NE / 8, 256>>>(p_hp, ei);
    gemm_mma<8, true, true, true, false, true><<<gemmBlocks, 256, SMEM>>>(
        p_s, p_hp, Wl2, Wr2, bl2, p_hp);                  // hp2 (in-place) + stats
    finalize_kernel<<<1, D>>>(g2w, g2b, g2a);
    final_kernel<<<finBlocks, 256>>>(p_hp, out, bres);
}

// round 10
// speedup vs baseline: 2.1357x; 1.2753x over previous
#include <cuda_runtime.h>
#include <cstdint>

#define NN 50000
#define NE 800000
#define D  128
#define EPSV 1e-5f

// ---------------- scratch ----------------
__device__ float g_s[(size_t)NN * D];      // aggregated (mean) features
__device__ float g_hp[(size_t)NN * D];     // pre-norm GEMM output
__device__ float g_xres[(size_t)NN * D];   // x @ Wres^T
__device__ float g_stats[2 * D];
__device__ float g_np[3 * D];              // a*mean | w*rsqrt(var+eps) | b
__device__ int   g_icnt[NN];
__device__ int   g_rowptr[NN + 1];
__device__ int   g_fill[NN];
__device__ int   g_adj[NE];
__device__ float g_Wc1[256 * 128];         // [n][k] tf32-rounded concat [Wl1|Wr1]
__device__ float g_Wc2[256 * 128];
__device__ float g_Wrt[128 * 128];         // [n][k] tf32-rounded Wres

// ---------------- tf32 helpers ----------------
__device__ __forceinline__ uint32_t f2tf32(float f) {
    uint32_t r;
    asm("cvt.rna.tf32.f32 %0, %1;" : "=r"(r) : "f"(f));
    return r;
}
__device__ __forceinline__ void mma_tf32(float* d, const uint32_t* a,
                                         uint32_t b0, uint32_t b1) {
    asm volatile(
        "mma.sync.aligned.m16n8k8.row.col.f32.tf32.tf32.f32 "
        "{%0,%1,%2,%3}, {%4,%5,%6,%7}, {%8,%9}, {%0,%1,%2,%3};"
        : "+f"(d[0]), "+f"(d[1]), "+f"(d[2]), "+f"(d[3])
        : "r"(a[0]), "r"(a[1]), "r"(a[2]), "r"(a[3]), "r"(b0), "r"(b1));
}
__device__ __forceinline__ uint32_t smem_u32(const void* p) {
    uint32_t a;
    asm("{ .reg .u64 t; cvta.to.shared.u64 t, %1; cvt.u32.u64 %0, t; }" : "=r"(a) : "l"(p));
    return a;
}
__device__ __forceinline__ void cp16(uint32_t dst, const void* src) {
    asm volatile("cp.async.cg.shared.global [%0], [%1], 16;" :: "r"(dst), "l"(src));
}
__device__ __forceinline__ void cp16z(uint32_t dst, const void* src, int sz) {
    asm volatile("cp.async.cg.shared.global [%0], [%1], 16, %2;"
                 :: "r"(dst), "l"(src), "r"(sz));
}

// ---------------- weight pre-conversion (tf32 round, concat layout) ----------
__global__ void prep_w(const float* __restrict__ Wl1, const float* __restrict__ Wr1,
                       const float* __restrict__ Wl2, const float* __restrict__ Wr2,
                       const float* __restrict__ Wres)
{
    int idx = blockIdx.x * blockDim.x + threadIdx.x;
    if (idx < 128 * 256) {
        int n = idx >> 8, k = idx & 255;
        float v1 = (k < D) ? Wl1[n * D + k] : Wr1[n * D + (k - D)];
        float v2 = (k < D) ? Wl2[n * D + k] : Wr2[n * D + (k - D)];
        g_Wc1[idx] = __uint_as_float(f2tf32(v1));
        g_Wc2[idx] = __uint_as_float(f2tf32(v2));
    } else if (idx < 128 * 256 + 128 * 128) {
        int t = idx - 128 * 256;
        g_Wrt[t] = __uint_as_float(f2tf32(Wres[t]));
    }
}

// ---------------- small zero (counters + stats) ----------------
__global__ void zero_kernel()
{
    int idx = blockIdx.x * blockDim.x + threadIdx.x;
    if (idx < NN) g_icnt[idx] = 0;
    if (idx < 2 * D) g_stats[idx] = 0.f;
}

// ---------------- CSR build ----------------
__global__ void count_kernel(const int* __restrict__ ei)
{
    int e = blockIdx.x * blockDim.x + threadIdx.x;
    if (e >= NE) return;
    int d = __ldg(ei + NE + e);
    if ((unsigned)d < NN) atomicAdd(&g_icnt[d], 1);
}

__global__ void scan_kernel()
{
    __shared__ int part[1024];
    const int t = threadIdx.x;
    const int CH = (NN + 1023) / 1024;   // 49
    int beg = t * CH;
    int end = min(beg + CH, NN);
    int s = 0;
    for (int i = beg; i < end; i++) s += g_icnt[i];
    part[t] = s;
    __syncthreads();
    for (int off = 1; off < 1024; off <<= 1) {
        int v = (t >= off) ? part[t - off] : 0;
        __syncthreads();
        part[t] += v;
        __syncthreads();
    }
    int ex = (t == 0) ? 0 : part[t - 1];
    for (int i = beg; i < end; i++) {
        g_rowptr[i] = ex;
        g_fill[i] = ex;
        ex += g_icnt[i];
    }
    if (t == 1023) g_rowptr[NN] = part[1023];
}

__global__ void fill_kernel(const int* __restrict__ ei)
{
    int e = blockIdx.x * blockDim.x + threadIdx.x;
    if (e >= NE) return;
    int s = __ldg(ei + e);
    int d = __ldg(ei + NE + e);
    if ((unsigned)s >= NN || (unsigned)d >= NN) return;
    int pos = atomicAdd(&g_fill[d], 1);
    g_adj[pos] = s;
}

// ---------------- CSR gather (mean aggregate); NORM applies graphnorm+relu ----
template <bool NORM>
__global__ void gather_kernel(const float* __restrict__ src)
{
    int w = (blockIdx.x * blockDim.x + threadIdx.x) >> 5;
    int lane = threadIdx.x & 31;
    if (w >= NN) return;
    int beg = g_rowptr[w];
    int end = g_rowptr[w + 1];
    float4 nm, nw, nb;
    if (NORM) {
        nm = __ldg(reinterpret_cast<const float4*>(g_np) + lane);
        nw = __ldg(reinterpret_cast<const float4*>(g_np + D) + lane);
        nb = __ldg(reinterpret_cast<const float4*>(g_np + 2 * D) + lane);
    }
    float4 acc = make_float4(0.f, 0.f, 0.f, 0.f);
#pragma unroll 4
    for (int j = beg; j < end; j++) {
        int s = __ldg(g_adj + j);
        float4 v = __ldg(reinterpret_cast<const float4*>(src + (size_t)s * D) + lane);
        if (NORM) {
            v.x = fmaxf(nw.x * (v.x - nm.x) + nb.x, 0.f);
            v.y = fmaxf(nw.y * (v.y - nm.y) + nb.y, 0.f);
            v.z = fmaxf(nw.z * (v.z - nm.z) + nb.z, 0.f);
            v.w = fmaxf(nw.w * (v.w - nm.w) + nb.w, 0.f);
        }
        acc.x += v.x; acc.y += v.y; acc.z += v.z; acc.w += v.w;
    }
    float inv = 1.0f / fmaxf((float)(end - beg), 1.0f);
    acc.x *= inv; acc.y *= inv; acc.z *= inv; acc.w *= inv;
    reinterpret_cast<float4*>(g_s + (size_t)w * D)[lane] = acc;
}

// ---------------- mma.sync tf32 GEMM ----------------
// out[NN,128] = [A0 | normA1?(A1)] @ Wt^T (+bias); Wt pre-converted tf32 [n][KS]
#define KP 36
#define BUFF (128 * KP)

template <int KC, bool CONCAT, bool STATS, bool NORMA1>
__global__ __launch_bounds__(256, 2)
void gemm_mma(const float* __restrict__ A0, const float* __restrict__ A1,
              const float* __restrict__ Wt,
              const float* __restrict__ bias, float* __restrict__ out)
{
    constexpr int KS = KC * 32;
    extern __shared__ float sm[];
    float* As  = sm;                 // [2][128][KP]
    float* Bs  = sm + 2 * BUFF;      // [2][128][KP]
    float* npS = sm + 4 * BUFF;      // [384]
    float* sumS = sm;                // stats scratch (reuse As after compute)
    float* sqS  = sm + 512;

    const uint32_t sA = smem_u32(As);
    const uint32_t sB = smem_u32(Bs);
    const int tid = threadIdx.x;
    const int wid = tid >> 5, lane = tid & 31;
    const int warpM = wid >> 1;
    const int warpN = wid & 1;
    const int gid = lane >> 2;
    const int tg  = lane & 3;
    const int rowBase = blockIdx.x * 128;

    if (NORMA1) {
        for (int i = tid; i < 3 * D; i += 256) npS[i] = g_np[i];
    }

    float acc[2][8][4];
#pragma unroll
    for (int m = 0; m < 2; m++)
#pragma unroll
        for (int n = 0; n < 8; n++)
#pragma unroll
            for (int q = 0; q < 4; q++) acc[m][n][q] = 0.f;

    auto issueChunk = [&](int kc, int buf) {
#pragma unroll
        for (int i = 0; i < 4; i++) {
            int f = tid + i * 256;
            int r = f >> 3;
            int kg = f & 7;
            int k = kc * 32 + kg * 4;
            uint32_t soff = (uint32_t)(buf * BUFF + r * KP + kg * 4) * 4u;
            int rg = rowBase + r;
            const float* gp;
            if (CONCAT && k >= D) gp = A1 + (size_t)rg * D + (k - D);
            else                  gp = A0 + (size_t)rg * D + k;
            int sz = 16;
            if (rg >= NN) { gp = A0; sz = 0; }
            cp16z(sA + soff, gp, sz);
            cp16(sB + soff, Wt + r * KS + k);
        }
        asm volatile("cp.async.commit_group;" ::: "memory");
    };

    issueChunk(0, 0);

#pragma unroll
    for (int kc = 0; kc < KC; kc++) {
        if (kc + 1 < KC) {
            issueChunk(kc + 1, (kc + 1) & 1);
            asm volatile("cp.async.wait_group 1;" ::: "memory");
        } else {
            asm volatile("cp.async.wait_group 0;" ::: "memory");
        }
        __syncthreads();

        const int buf = kc & 1;
        const float* ab = &As[buf * BUFF];
        const float* bb = &Bs[buf * BUFF];
        const bool isA1 = CONCAT && (kc >= 4);

#pragma unroll
        for (int ks = 0; ks < 4; ks++) {
            const int kb = ks * 8;
            float nm0 = 0.f, nw0 = 1.f, nb0 = 0.f, nm1 = 0.f, nw1 = 1.f, nb1 = 0.f;
            if (NORMA1 && isA1) {
                int c0 = (kc - 4) * 32 + kb + tg;
                int c1 = c0 + 4;
                nm0 = npS[c0]; nw0 = npS[D + c0]; nb0 = npS[2 * D + c0];
                nm1 = npS[c1]; nw1 = npS[D + c1]; nb1 = npS[2 * D + c1];
            }
            uint32_t a[2][4];
#pragma unroll
            for (int m = 0; m < 2; m++) {
                int r1 = warpM * 32 + m * 16 + gid;
                int r2 = r1 + 8;
                float v0 = ab[r1 * KP + kb + tg];
                float v1 = ab[r2 * KP + kb + tg];
                float v2 = ab[r1 * KP + kb + tg + 4];
                float v3 = ab[r2 * KP + kb + tg + 4];
                if (NORMA1 && isA1) {
                    v0 = fmaxf(nw0 * (v0 - nm0) + nb0, 0.f);
                    v1 = fmaxf(nw0 * (v1 - nm0) + nb0, 0.f);
                    v2 = fmaxf(nw1 * (v2 - nm1) + nb1, 0.f);
                    v3 = fmaxf(nw1 * (v3 - nm1) + nb1, 0.f);
                }
                a[m][0] = f2tf32(v0); a[m][1] = f2tf32(v1);
                a[m][2] = f2tf32(v2); a[m][3] = f2tf32(v3);
            }
#pragma unroll
            for (int n = 0; n < 8; n++) {
                int c = warpN * 64 + n * 8 + gid;
                uint32_t b0 = __float_as_uint(bb[c * KP + kb + tg]);      // pre-tf32
                uint32_t b1 = __float_as_uint(bb[c * KP + kb + tg + 4]);
                mma_tf32(acc[0][n], a[0], b0, b1);
                mma_tf32(acc[1][n], a[1], b0, b1);
            }
        }
        __syncthreads();
    }

    // ---- epilogue: bias + store + (stats) ----
    const bool hasBias = (bias != nullptr);
    bool valid[2][2];
#pragma unroll
    for (int m = 0; m < 2; m++)
#pragma unroll
        for (int h = 0; h < 2; h++)
            valid[m][h] = (rowBase + warpM * 32 + m * 16 + h * 8 + gid) < NN;

#pragma unroll
    for (int n = 0; n < 8; n++) {
        int col = warpN * 64 + n * 8 + tg * 2;
        float b0 = hasBias ? __ldg(bias + col) : 0.f;
        float b1 = hasBias ? __ldg(bias + col + 1) : 0.f;
        float s0 = 0.f, s1 = 0.f, q0 = 0.f, q1 = 0.f;
#pragma unroll
        for (int m = 0; m < 2; m++) {
#pragma unroll
            for (int h = 0; h < 2; h++) {
                if (valid[m][h]) {
                    float v0 = acc[m][n][h * 2 + 0] + b0;
                    float v1 = acc[m][n][h * 2 + 1] + b1;
                    int row = rowBase + warpM * 32 + m * 16 + h * 8 + gid;
                    float2 st; st.x = v0; st.y = v1;
                    *reinterpret_cast<float2*>(out + (size_t)row * D + col) = st;
                    if (STATS) { s0 += v0; q0 += v0 * v0; s1 += v1; q1 += v1 * v1; }
                }
            }
        }
        if (STATS) {
#pragma unroll
            for (int sh = 4; sh <= 16; sh <<= 1) {
                s0 += __shfl_xor_sync(0xFFFFFFFFu, s0, sh);
                s1 += __shfl_xor_sync(0xFFFFFFFFu, s1, sh);
                q0 += __shfl_xor_sync(0xFFFFFFFFu, q0, sh);
                q1 += __shfl_xor_sync(0xFFFFFFFFu, q1, sh);
            }
            if (gid == 0) {
                sumS[warpM * 128 + col]     = s0;
                sumS[warpM * 128 + col + 1] = s1;
                sqS[warpM * 128 + col]      = q0;
                sqS[warpM * 128 + col + 1]  = q1;
            }
        }
    }

    if (STATS) {
        __syncthreads();
        if (tid < D) {
            float s = sumS[tid] + sumS[128 + tid] + sumS[256 + tid] + sumS[384 + tid];
            float q = sqS[tid] + sqS[128 + tid] + sqS[256 + tid] + sqS[384 + tid];
            atomicAdd(&g_stats[tid], s);
            atomicAdd(&g_stats[D + tid], q);
        }
    }
}

// ---------------- GraphNorm finalize (+ reset stats) ----------------
__global__ void finalize_kernel(const float* __restrict__ w,
                                const float* __restrict__ b,
                                const float* __restrict__ a)
{
    int j = threadIdx.x;
    const float invN = 1.0f / (float)NN;
    float mean = g_stats[j] * invN;
    float ex2  = g_stats[D + j] * invN;
    float aj = a[j];
    float var = ex2 - (2.0f * aj - aj * aj) * mean * mean;
    g_np[j]         = aj * mean;
    g_np[D + j]     = w[j] * rsqrtf(var + EPSV);
    g_np[2 * D + j] = b[j];
    g_stats[j] = 0.f;
    g_stats[D + j] = 0.f;
}

// ---------------- final: norm2 + relu + residual + bres -> out ----------------
__global__ void final_kernel(const float* __restrict__ h, float* __restrict__ o,
                             const float* __restrict__ bres)
{
    int idx = blockIdx.x * blockDim.x + threadIdx.x;
    if (idx >= NN * (D / 4)) return;
    int col = (idx & 31) * 4;
    float4 v = reinterpret_cast<const float4*>(h)[idx];
    float4 xr = reinterpret_cast<const float4*>(g_xres)[idx];
    float4 r;
    r.x = fmaxf(g_np[D + col + 0] * (v.x - g_np[col + 0]) + g_np[2 * D + col + 0], 0.f)
          + xr.x + __ldg(bres + col + 0);
    r.y = fmaxf(g_np[D + col + 1] * (v.y - g_np[col + 1]) + g_np[2 * D + col + 1], 0.f)
          + xr.y + __ldg(bres + col + 1);
    r.z = fmaxf(g_np[D + col + 2] * (v.z - g_np[col + 2]) + g_np[2 * D + col + 2], 0.f)
          + xr.z + __ldg(bres + col + 2);
    r.w = fmaxf(g_np[D + col + 3] * (v.w - g_np[col + 3]) + g_np[2 * D + col + 3], 0.f)
          + xr.w + __ldg(bres + col + 3);
    reinterpret_cast<float4*>(o)[idx] = r;
}

// ---------------- launch ----------------
extern "C" void kernel_launch(void* const* d_in, const int* in_sizes, int n_in,
                              void* d_out, int out_size)
{
    const float* x    = (const float*)d_in[0];
    const int*   ei   = (const int*)d_in[1];
    const float* Wl1  = (const float*)d_in[2];
    const float* bl1  = (const float*)d_in[3];
    const float* Wr1  = (const float*)d_in[4];
    const float* Wl2  = (const float*)d_in[5];
    const float* bl2  = (const float*)d_in[6];
    const float* Wr2  = (const float*)d_in[7];
    const float* g1w  = (const float*)d_in[8];
    const float* g1b  = (const float*)d_in[9];
    const float* g1a  = (const float*)d_in[10];
    const float* g2w  = (const float*)d_in[11];
    const float* g2b  = (const float*)d_in[12];
    const float* g2a  = (const float*)d_in[13];
    const float* Wres = (const float*)d_in[14];
    const float* bres = (const float*)d_in[15];
    float* out = (float*)d_out;

    float *p_s, *p_hp, *p_xres, *p_Wc1, *p_Wc2, *p_Wrt;
    cudaGetSymbolAddress((void**)&p_s,    g_s);
    cudaGetSymbolAddress((void**)&p_hp,   g_hp);
    cudaGetSymbolAddress((void**)&p_xres, g_xres);
    cudaGetSymbolAddress((void**)&p_Wc1,  g_Wc1);
    cudaGetSymbolAddress((void**)&p_Wc2,  g_Wc2);
    cudaGetSymbolAddress((void**)&p_Wrt,  g_Wrt);

    const int SMEM = (4 * BUFF + 3 * D) * (int)sizeof(float);  // 75264
    cudaFuncSetAttribute((const void*)gemm_mma<8, true, true, false>,
                         cudaFuncAttributeMaxDynamicSharedMemorySize, SMEM);
    cudaFuncSetAttribute((const void*)gemm_mma<8, true, true, true>,
                         cudaFuncAttributeMaxDynamicSharedMemorySize, SMEM);
    cudaFuncSetAttribute((const void*)gemm_mma<4, false, false, false>,
                         cudaFuncAttributeMaxDynamicSharedMemorySize, SMEM);

    const int gemmBlocks = (NN + 127) / 128;          // 391
    const int gathBlocks = (NN + 7) / 8;              // 6250 (8 warps/block)
    const int edgeBlocks = (NE + 255) / 256;
    const int finBlocks  = (NN * (D / 4) + 255) / 256;

    // ---- prep + CSR build (reused by both layers) ----
    prep_w<<<(128 * 256 + 128 * 128 + 255) / 256, 256>>>(Wl1, Wr1, Wl2, Wr2, Wres);
    zero_kernel<<<(NN + 255) / 256, 256>>>();
    count_kernel<<<edgeBlocks, 256>>>(ei);
    scan_kernel<<<1, 1024>>>();
    fill_kernel<<<edgeBlocks, 256>>>(ei);

    // ---- layer 1 ----
    gather_kernel<false><<<gathBlocks, 256>>>(x);
    gemm_mma<8, true, true, false><<<gemmBlocks, 256, SMEM>>>(p_s, x, p_Wc1, bl1, p_hp);
    gemm_mma<4, false, false, false><<<gemmBlocks, 256, SMEM>>>(x, x, p_Wrt, nullptr, p_xres);
    finalize_kernel<<<1, D>>>(g1w, g1b, g1a);

    // ---- layer 2 (h1 never materialized) ----
    gather_kernel<true><<<gathBlocks, 256>>>(p_hp);
    gemm_mma<8, true, true, true><<<gemmBlocks, 256, SMEM>>>(p_s, p_hp, p_Wc2, bl2, p_hp);
    finalize_kernel<<<1, D>>>(g2w, g2b, g2a);
    final_kernel<<<finBlocks, 256>>>(p_hp, out, bres);
}

// round 11
// speedup vs baseline: 2.8946x; 1.3553x over previous
#include <cuda_runtime.h>
#include <cstdint>

#define NN 50000
#define NE 800000
#define D  128
#define EPSV 1e-5f
#define NBLK 196   // ceil(NN/256)

// ---------------- scratch ----------------
__device__ float g_s[(size_t)NN * D];      // aggregated (mean) features
__device__ float g_hp[(size_t)NN * D];     // pre-norm GEMM output
__device__ float g_xres[(size_t)NN * D];   // x @ Wres^T
__device__ float g_stats[2 * D];
__device__ float g_np[3 * D];              // a*mean | w*rsqrt(var+eps) | b
__device__ int   g_icnt[NN];
__device__ int   g_rowptr[NN + 1];
__device__ int   g_fill[NN];
__device__ int   g_adj[NE];
__device__ int   g_bsum[NBLK];
__device__ int   g_boff[NBLK];
__device__ float g_Wc1[256 * 128];         // [n][k] tf32-rounded concat [Wl1|Wr1]
__device__ float g_Wc2[256 * 128];
__device__ float g_Wrt[128 * 128];         // [n][k] tf32-rounded Wres

// ---------------- tf32 helpers ----------------
__device__ __forceinline__ uint32_t f2tf32(float f) {
    uint32_t r;
    asm("cvt.rna.tf32.f32 %0, %1;" : "=r"(r) : "f"(f));
    return r;
}
__device__ __forceinline__ void mma_tf32(float* d, const uint32_t* a,
                                         uint32_t b0, uint32_t b1) {
    asm volatile(
        "mma.sync.aligned.m16n8k8.row.col.f32.tf32.tf32.f32 "
        "{%0,%1,%2,%3}, {%4,%5,%6,%7}, {%8,%9}, {%0,%1,%2,%3};"
        : "+f"(d[0]), "+f"(d[1]), "+f"(d[2]), "+f"(d[3])
        : "r"(a[0]), "r"(a[1]), "r"(a[2]), "r"(a[3]), "r"(b0), "r"(b1));
}
__device__ __forceinline__ uint32_t smem_u32(const void* p) {
    uint32_t a;
    asm("{ .reg .u64 t; cvta.to.shared.u64 t, %1; cvt.u32.u64 %0, t; }" : "=r"(a) : "l"(p));
    return a;
}
__device__ __forceinline__ void cp16(uint32_t dst, const void* src) {
    asm volatile("cp.async.cg.shared.global [%0], [%1], 16;" :: "r"(dst), "l"(src));
}
__device__ __forceinline__ void cp16z(uint32_t dst, const void* src, int sz) {
    asm volatile("cp.async.cg.shared.global [%0], [%1], 16, %2;"
                 :: "r"(dst), "l"(src), "r"(sz));
}

// ---------------- weight pre-conversion (tf32 round, concat layout) ----------
__global__ void prep_w(const float* __restrict__ Wl1, const float* __restrict__ Wr1,
                       const float* __restrict__ Wl2, const float* __restrict__ Wr2,
                       const float* __restrict__ Wres)
{
    int idx = blockIdx.x * blockDim.x + threadIdx.x;
    if (idx < 128 * 256) {
        int n = idx >> 8, k = idx & 255;
        float v1 = (k < D) ? Wl1[n * D + k] : Wr1[n * D + (k - D)];
        float v2 = (k < D) ? Wl2[n * D + k] : Wr2[n * D + (k - D)];
        g_Wc1[idx] = __uint_as_float(f2tf32(v1));
        g_Wc2[idx] = __uint_as_float(f2tf32(v2));
    } else if (idx < 128 * 256 + 128 * 128) {
        int t = idx - 128 * 256;
        g_Wrt[t] = __uint_as_float(f2tf32(Wres[t]));
    }
}

// ---------------- small zero (counters + stats) ----------------
__global__ void zero_kernel()
{
    int idx = blockIdx.x * blockDim.x + threadIdx.x;
    if (idx < NN) g_icnt[idx] = 0;
    if (idx < 2 * D) g_stats[idx] = 0.f;
}

// ---------------- CSR build ----------------
__global__ void count_kernel(const int* __restrict__ ei)
{
    int e = blockIdx.x * blockDim.x + threadIdx.x;
    if (e >= NE) return;
    int d = __ldg(ei + NE + e);
    if ((unsigned)d < NN) atomicAdd(&g_icnt[d], 1);
}

// phase 1: per-block sums
__global__ void bsum_kernel()
{
    __shared__ int sh[256];
    int t = threadIdx.x;
    int i = blockIdx.x * 256 + t;
    int v = (i < NN) ? g_icnt[i] : 0;
    sh[t] = v;
    __syncthreads();
    for (int off = 128; off > 0; off >>= 1) {
        if (t < off) sh[t] += sh[t + off];
        __syncthreads();
    }
    if (t == 0) g_bsum[blockIdx.x] = sh[0];
}

// phase 2: exclusive scan of NBLK block sums (1 block)
__global__ void bscan_kernel()
{
    __shared__ int sh[256];
    int t = threadIdx.x;
    int v = (t < NBLK) ? g_bsum[t] : 0;
    sh[t] = v;
    __syncthreads();
#pragma unroll
    for (int off = 1; off < 256; off <<= 1) {
        int u = (t >= off) ? sh[t - off] : 0;
        __syncthreads();
        sh[t] += u;
        __syncthreads();
    }
    if (t < NBLK) g_boff[t] = sh[t] - v;   // exclusive
}

// phase 3: per-block scan + offset -> rowptr, fill
__global__ void rowptr_kernel()
{
    __shared__ int sh[256];
    int t = threadIdx.x;
    int i = blockIdx.x * 256 + t;
    int v = (i < NN) ? g_icnt[i] : 0;
    sh[t] = v;
    __syncthreads();
#pragma unroll
    for (int off = 1; off < 256; off <<= 1) {
        int u = (t >= off) ? sh[t - off] : 0;
        __syncthreads();
        sh[t] += u;
        __syncthreads();
    }
    if (i < NN) {
        int ex = g_boff[blockIdx.x] + sh[t] - v;   // exclusive prefix
        g_rowptr[i] = ex;
        g_fill[i] = ex;
        if (i == NN - 1) g_rowptr[NN] = ex + v;
    }
}

__global__ void fill_kernel(const int* __restrict__ ei)
{
    int e = blockIdx.x * blockDim.x + threadIdx.x;
    if (e >= NE) return;
    int s = __ldg(ei + e);
    int d = __ldg(ei + NE + e);
    if ((unsigned)s >= NN || (unsigned)d >= NN) return;
    int pos = atomicAdd(&g_fill[d], 1);
    g_adj[pos] = s;
}

// ---------------- CSR gather (mean aggregate); NORM applies graphnorm+relu ----
template <bool NORM>
__global__ void gather_kernel(const float* __restrict__ src)
{
    int w = (blockIdx.x * blockDim.x + threadIdx.x) >> 5;
    int lane = threadIdx.x & 31;
    if (w >= NN) return;
    int beg = g_rowptr[w];
    int end = g_rowptr[w + 1];
    float4 nm, nw, nb;
    if (NORM) {
        nm = __ldg(reinterpret_cast<const float4*>(g_np) + lane);
        nw = __ldg(reinterpret_cast<const float4*>(g_np + D) + lane);
        nb = __ldg(reinterpret_cast<const float4*>(g_np + 2 * D) + lane);
    }
    float4 acc = make_float4(0.f, 0.f, 0.f, 0.f);
#pragma unroll 4
    for (int j = beg; j < end; j++) {
        int s = __ldg(g_adj + j);
        float4 v = __ldg(reinterpret_cast<const float4*>(src + (size_t)s * D) + lane);
        if (NORM) {
            v.x = fmaxf(nw.x * (v.x - nm.x) + nb.x, 0.f);
            v.y = fmaxf(nw.y * (v.y - nm.y) + nb.y, 0.f);
            v.z = fmaxf(nw.z * (v.z - nm.z) + nb.z, 0.f);
            v.w = fmaxf(nw.w * (v.w - nm.w) + nb.w, 0.f);
        }
        acc.x += v.x; acc.y += v.y; acc.z += v.z; acc.w += v.w;
    }
    float inv = 1.0f / fmaxf((float)(end - beg), 1.0f);
    acc.x *= inv; acc.y *= inv; acc.z *= inv; acc.w *= inv;
    reinterpret_cast<float4*>(g_s + (size_t)w * D)[lane] = acc;
}

// ---------------- mma.sync tf32 GEMM ----------------
// out[NN,128] = [A0 | normA1?(A1)] @ Wt^T (+bias); Wt pre-converted tf32 [n][KS]
#define KP 36
#define BUFF (128 * KP)

template <int KC, bool CONCAT, bool STATS, bool NORMA1>
__global__ __launch_bounds__(256, 2)
void gemm_mma(const float* __restrict__ A0, const float* __restrict__ A1,
              const float* __restrict__ Wt,
              const float* __restrict__ bias, float* __restrict__ out)
{
    constexpr int KS = KC * 32;
    extern __shared__ float sm[];
    float* As  = sm;                 // [2][128][KP]
    float* Bs  = sm + 2 * BUFF;      // [2][128][KP]
    float* npS = sm + 4 * BUFF;      // [384]
    float* sumS = sm;                // stats scratch (reuse As after compute)
    float* sqS  = sm + 512;

    const uint32_t sA = smem_u32(As);
    const uint32_t sB = smem_u32(Bs);
    const int tid = threadIdx.x;
    const int wid = tid >> 5, lane = tid & 31;
    const int warpM = wid >> 1;
    const int warpN = wid & 1;
    const int gid = lane >> 2;
    const int tg  = lane & 3;
    const int rowBase = blockIdx.x * 128;

    if (NORMA1) {
        for (int i = tid; i < 3 * D; i += 256) npS[i] = g_np[i];
    }

    float acc[2][8][4];
#pragma unroll
    for (int m = 0; m < 2; m++)
#pragma unroll
        for (int n = 0; n < 8; n++)
#pragma unroll
            for (int q = 0; q < 4; q++) acc[m][n][q] = 0.f;

    auto issueChunk = [&](int kc, int buf) {
#pragma unroll
        for (int i = 0; i < 4; i++) {
            int f = tid + i * 256;
            int r = f >> 3;
            int kg = f & 7;
            int k = kc * 32 + kg * 4;
            uint32_t soff = (uint32_t)(buf * BUFF + r * KP + kg * 4) * 4u;
            int rg = rowBase + r;
            const float* gp;
            if (CONCAT && k >= D) gp = A1 + (size_t)rg * D + (k - D);
            else                  gp = A0 + (size_t)rg * D + k;
            int sz = 16;
            if (rg >= NN) { gp = A0; sz = 0; }
            cp16z(sA + soff, gp, sz);
            cp16(sB + soff, Wt + r * KS + k);
        }
        asm volatile("cp.async.commit_group;" ::: "memory");
    };

    issueChunk(0, 0);

#pragma unroll
    for (int kc = 0; kc < KC; kc++) {
        if (kc + 1 < KC) {
            issueChunk(kc + 1, (kc + 1) & 1);
            asm volatile("cp.async.wait_group 1;" ::: "memory");
        } else {
            asm volatile("cp.async.wait_group 0;" ::: "memory");
        }
        __syncthreads();

        const int buf = kc & 1;
        const float* ab = &As[buf * BUFF];
        const float* bb = &Bs[buf * BUFF];
        const bool isA1 = CONCAT && (kc >= 4);

#pragma unroll
        for (int ks = 0; ks < 4; ks++) {
            const int kb = ks * 8;
            float nm0 = 0.f, nw0 = 1.f, nb0 = 0.f, nm1 = 0.f, nw1 = 1.f, nb1 = 0.f;
            if (NORMA1 && isA1) {
                int c0 = (kc - 4) * 32 + kb + tg;
                int c1 = c0 + 4;
                nm0 = npS[c0]; nw0 = npS[D + c0]; nb0 = npS[2 * D + c0];
                nm1 = npS[c1]; nw1 = npS[D + c1]; nb1 = npS[2 * D + c1];
            }
            uint32_t a[2][4];
#pragma unroll
            for (int m = 0; m < 2; m++) {
                int r1 = warpM * 32 + m * 16 + gid;
                int r2 = r1 + 8;
                float v0 = ab[r1 * KP + kb + tg];
                float v1 = ab[r2 * KP + kb + tg];
                float v2 = ab[r1 * KP + kb + tg + 4];
                float v3 = ab[r2 * KP + kb + tg + 4];
                if (NORMA1 && isA1) {
                    v0 = fmaxf(nw0 * (v0 - nm0) + nb0, 0.f);
                    v1 = fmaxf(nw0 * (v1 - nm0) + nb0, 0.f);
                    v2 = fmaxf(nw1 * (v2 - nm1) + nb1, 0.f);
                    v3 = fmaxf(nw1 * (v3 - nm1) + nb1, 0.f);
                }
                a[m][0] = f2tf32(v0); a[m][1] = f2tf32(v1);
                a[m][2] = f2tf32(v2); a[m][3] = f2tf32(v3);
            }
#pragma unroll
            for (int n = 0; n < 8; n++) {
                int c = warpN * 64 + n * 8 + gid;
                uint32_t b0 = __float_as_uint(bb[c * KP + kb + tg]);      // pre-tf32
                uint32_t b1 = __float_as_uint(bb[c * KP + kb + tg + 4]);
                mma_tf32(acc[0][n], a[0], b0, b1);
                mma_tf32(acc[1][n], a[1], b0, b1);
            }
        }
        __syncthreads();
    }

    // ---- epilogue: bias + store + (stats) ----
    const bool hasBias = (bias != nullptr);
    bool valid[2][2];
#pragma unroll
    for (int m = 0; m < 2; m++)
#pragma unroll
        for (int h = 0; h < 2; h++)
            valid[m][h] = (rowBase + warpM * 32 + m * 16 + h * 8 + gid) < NN;

#pragma unroll
    for (int n = 0; n < 8; n++) {
        int col = warpN * 64 + n * 8 + tg * 2;
        float b0 = hasBias ? __ldg(bias + col) : 0.f;
        float b1 = hasBias ? __ldg(bias + col + 1) : 0.f;
        float s0 = 0.f, s1 = 0.f, q0 = 0.f, q1 = 0.f;
#pragma unroll
        for (int m = 0; m < 2; m++) {
#pragma unroll
            for (int h = 0; h < 2; h++) {
                if (valid[m][h]) {
                    float v0 = acc[m][n][h * 2 + 0] + b0;
                    float v1 = acc[m][n][h * 2 + 1] + b1;
                    int row = rowBase + warpM * 32 + m * 16 + h * 8 + gid;
                    float2 st; st.x = v0; st.y = v1;
                    *reinterpret_cast<float2*>(out + (size_t)row * D + col) = st;
                    if (STATS) { s0 += v0; q0 += v0 * v0; s1 += v1; q1 += v1 * v1; }
                }
            }
        }
        if (STATS) {
#pragma unroll
            for (int sh = 4; sh <= 16; sh <<= 1) {
                s0 += __shfl_xor_sync(0xFFFFFFFFu, s0, sh);
                s1 += __shfl_xor_sync(0xFFFFFFFFu, s1, sh);
                q0 += __shfl_xor_sync(0xFFFFFFFFu, q0, sh);
                q1 += __shfl_xor_sync(0xFFFFFFFFu, q1, sh);
            }
            if (gid == 0) {
                sumS[warpM * 128 + col]     = s0;
                sumS[warpM * 128 + col + 1] = s1;
                sqS[warpM * 128 + col]      = q0;
                sqS[warpM * 128 + col + 1]  = q1;
            }
        }
    }

    if (STATS) {
        __syncthreads();
        if (tid < D) {
            float s = sumS[tid] + sumS[128 + tid] + sumS[256 + tid] + sumS[384 + tid];
            float q = sqS[tid] + sqS[128 + tid] + sqS[256 + tid] + sqS[384 + tid];
            atomicAdd(&g_stats[tid], s);
            atomicAdd(&g_stats[D + tid], q);
        }
    }
}

// ---------------- GraphNorm finalize (+ reset stats) ----------------
__global__ void finalize_kernel(const float* __restrict__ w,
                                const float* __restrict__ b,
                                const float* __restrict__ a)
{
    int j = threadIdx.x;
    const float invN = 1.0f / (float)NN;
    float mean = g_stats[j] * invN;
    float ex2  = g_stats[D + j] * invN;
    float aj = a[j];
    float var = ex2 - (2.0f * aj - aj * aj) * mean * mean;
    g_np[j]         = aj * mean;
    g_np[D + j]     = w[j] * rsqrtf(var + EPSV);
    g_np[2 * D + j] = b[j];
    g_stats[j] = 0.f;
    g_stats[D + j] = 0.f;
}

// ---------------- final: norm2 + relu + residual + bres -> out ----------------
__global__ void final_kernel(const float* __restrict__ h, float* __restrict__ o,
                             const float* __restrict__ bres)
{
    int idx = blockIdx.x * blockDim.x + threadIdx.x;
    if (idx >= NN * (D / 4)) return;
    int col = (idx & 31) * 4;
    float4 v = reinterpret_cast<const float4*>(h)[idx];
    float4 xr = reinterpret_cast<const float4*>(g_xres)[idx];
    float4 r;
    r.x = fmaxf(g_np[D + col + 0] * (v.x - g_np[col + 0]) + g_np[2 * D + col + 0], 0.f)
          + xr.x + __ldg(bres + col + 0);
    r.y = fmaxf(g_np[D + col + 1] * (v.y - g_np[col + 1]) + g_np[2 * D + col + 1], 0.f)
          + xr.y + __ldg(bres + col + 1);
    r.z = fmaxf(g_np[D + col + 2] * (v.z - g_np[col + 2]) + g_np[2 * D + col + 2], 0.f)
          + xr.z + __ldg(bres + col + 2);
    r.w = fmaxf(g_np[D + col + 3] * (v.w - g_np[col + 3]) + g_np[2 * D + col + 3], 0.f)
          + xr.w + __ldg(bres + col + 3);
    reinterpret_cast<float4*>(o)[idx] = r;
}

// ---------------- launch ----------------
extern "C" void kernel_launch(void* const* d_in, const int* in_sizes, int n_in,
                              void* d_out, int out_size)
{
    const float* x    = (const float*)d_in[0];
    const int*   ei   = (const int*)d_in[1];
    const float* Wl1  = (const float*)d_in[2];
    const float* bl1  = (const float*)d_in[3];
    const float* Wr1  = (const float*)d_in[4];
    const float* Wl2  = (const float*)d_in[5];
    const float* bl2  = (const float*)d_in[6];
    const float* Wr2  = (const float*)d_in[7];
    const float* g1w  = (const float*)d_in[8];
    const float* g1b  = (const float*)d_in[9];
    const float* g1a  = (const float*)d_in[10];
    const float* g2w  = (const float*)d_in[11];
    const float* g2b  = (const float*)d_in[12];
    const float* g2a  = (const float*)d_in[13];
    const float* Wres = (const float*)d_in[14];
    const float* bres = (const float*)d_in[15];
    float* out = (float*)d_out;

    float *p_s, *p_hp, *p_xres, *p_Wc1, *p_Wc2, *p_Wrt;
    cudaGetSymbolAddress((void**)&p_s,    g_s);
    cudaGetSymbolAddress((void**)&p_hp,   g_hp);
    cudaGetSymbolAddress((void**)&p_xres, g_xres);
    cudaGetSymbolAddress((void**)&p_Wc1,  g_Wc1);
    cudaGetSymbolAddress((void**)&p_Wc2,  g_Wc2);
    cudaGetSymbolAddress((void**)&p_Wrt,  g_Wrt);

    const int SMEM = (4 * BUFF + 3 * D) * (int)sizeof(float);  // 75264
    cudaFuncSetAttribute((const void*)gemm_mma<8, true, true, false>,
                         cudaFuncAttributeMaxDynamicSharedMemorySize, SMEM);
    cudaFuncSetAttribute((const void*)gemm_mma<8, true, true, true>,
                         cudaFuncAttributeMaxDynamicSharedMemorySize, SMEM);
    cudaFuncSetAttribute((const void*)gemm_mma<4, false, false, false>,
                         cudaFuncAttributeMaxDynamicSharedMemorySize, SMEM);

    const int gemmBlocks = (NN + 127) / 128;          // 391
    const int gathBlocks = (NN + 7) / 8;              // 6250 (8 warps/block)
    const int edgeBlocks = (NE + 255) / 256;
    const int finBlocks  = (NN * (D / 4) + 255) / 256;

    // ---- prep + CSR build (parallel scan; reused by both layers) ----
    prep_w<<<(128 * 256 + 128 * 128 + 255) / 256, 256>>>(Wl1, Wr1, Wl2, Wr2, Wres);
    zero_kernel<<<(NN + 255) / 256, 256>>>();
    count_kernel<<<edgeBlocks, 256>>>(ei);
    bsum_kernel<<<NBLK, 256>>>();
    bscan_kernel<<<1, 256>>>();
    rowptr_kernel<<<NBLK, 256>>>();
    fill_kernel<<<edgeBlocks, 256>>>(ei);

    // ---- layer 1 ----
    gather_kernel<false><<<gathBlocks, 256>>>(x);
    gemm_mma<8, true, true, false><<<gemmBlocks, 256, SMEM>>>(p_s, x, p_Wc1, bl1, p_hp);
    gemm_mma<4, false, false, false><<<gemmBlocks, 256, SMEM>>>(x, x, p_Wrt, nullptr, p_xres);
    finalize_kernel<<<1, D>>>(g1w, g1b, g1a);

    // ---- layer 2 (h1 never materialized) ----
    gather_kernel<true><<<gathBlocks, 256>>>(p_hp);
    gemm_mma<8, true, true, true><<<gemmBlocks, 256, SMEM>>>(p_s, p_hp, p_Wc2, bl2, p_hp);
    finalize_kernel<<<1, D>>>(g2w, g2b, g2a);
    final_kernel<<<finBlocks, 256>>>(p_hp, out, bres);
}